// round 3
// baseline (speedup 1.0000x reference)
#include <cuda_runtime.h>
#include <cstdint>

#define HH 512
#define WW 512
#define WORDS 16
#define SLAB 128
#define HALO 3
#define NTH 256
#define NWARPS (NTH / 32)
#define NOFF 12
#define NB 128
#define SLABS (HH / SLAB)

// zero-initialized; every use is paired with a reset -> deterministic replays
__device__ int g_cnt[NB * NOFF * 2];     // [image][offset]{diff, n11}
__device__ unsigned g_arrive[NB];

__global__ __launch_bounds__(NTH, 6)
void glcm_fused(const float* __restrict__ in, float* __restrict__ out)
{
    constexpr int RS[NOFF] = {0, 1, 1, 1, 0, 2, 2, 2, 0, 3, 3, 3};
    constexpr int CS[NOFF] = {1, 1, 0, -1, 2, 2, 0, -2, 3, 3, 0, -3};

    __shared__ unsigned sm[(SLAB + HALO) * WORDS + WORDS];  // + guard row
    __shared__ int s_diff[NOFF];
    __shared__ int s_n11[NOFF];
    __shared__ int s_last;

    const int tid  = threadIdx.x;
    const int lane = tid & 31;
    const int warp = tid >> 5;
    const int r0   = blockIdx.x * SLAB;
    const int b    = blockIdx.y;

    if (tid < NOFF) { s_diff[tid] = 0; s_n11[tid] = 0; }

    // ---- pack sign bits: rows [r0, r0+nload) -> bit-plane in SMEM ----------
    const int nload = min(SLAB + HALO, HH - r0);
    const float4* img4 = reinterpret_cast<const float4*>(
        in + ((size_t)b * HH + r0) * WW);
    const int NG = nload * 4;                     // 128-float groups

    #pragma unroll 4
    for (int g = warp; g < NG; g += NWARPS) {
        float4 v = img4[g * 32 + lane];
        unsigned nib = (v.x > 0.0f ? 1u : 0u)
                     | (v.y > 0.0f ? 2u : 0u)
                     | (v.z > 0.0f ? 4u : 0u)
                     | (v.w > 0.0f ? 8u : 0u);
        unsigned pack = nib << ((lane & 7) * 4);
        pack |= __shfl_xor_sync(0xffffffffu, pack, 1);
        pack |= __shfl_xor_sync(0xffffffffu, pack, 2);
        pack |= __shfl_xor_sync(0xffffffffu, pack, 4);
        if ((lane & 7) == 0) sm[g * 4 + (lane >> 3)] = pack;
    }
    __syncthreads();

    // ---- fused single pass: all 12 offsets per word ------------------------
    // a-row validity limits per row-offset R (only last slab clips)
    const int rl1 = min(SLAB, HH - 1 - r0);
    const int rl2 = min(SLAB, HH - 2 - r0);
    const int rl3 = min(SLAB, HH - 3 - r0);

    unsigned acc[NOFF];
    #pragma unroll
    for (int o = 0; o < NOFF; ++o) acc[o] = 0;

    #pragma unroll 2
    for (int i = tid; i < SLAB * WORDS; i += NTH) {
        const int w   = i & (WORDS - 1);
        const int row = i >> 4;
        const bool lastw  = (w == WORDS - 1);
        const bool firstw = (w == 0);

        const unsigned A = sm[i];

        #pragma unroll
        for (int o = 0; o < NOFF; ++o) {
            const int R = RS[o];
            const int C = CS[o];
            const int bi = i + R * WORDS;

            unsigned B;
            if (C > 0)       B = __funnelshift_r(sm[bi], sm[bi + 1], C);
            else if (C < 0)  B = __funnelshift_l(sm[bi - 1], sm[bi], -C);
            else             B = sm[bi];

            unsigned m = 0xffffffffu;
            if (C > 0 && lastw)  m = 0xffffffffu >> C;
            if (C < 0 && firstw) m = 0xffffffffu << (-C);
            if (R == 1 && row >= rl1) m = 0u;
            if (R == 2 && row >= rl2) m = 0u;
            if (R == 3 && row >= rl3) m = 0u;

            acc[o] += (unsigned)(__popc((A ^ B) & m) << 16)
                    |  (unsigned)__popc((A & B) & m);
        }
    }

    #pragma unroll
    for (int o = 0; o < NOFF; ++o) {
        unsigned v = __reduce_add_sync(0xffffffffu, acc[o]);
        if (lane == 0) {
            atomicAdd(&s_diff[o], (int)(v >> 16));
            atomicAdd(&s_n11[o],  (int)(v & 0xffffu));
        }
    }
    __syncthreads();

    if (tid < NOFF) {
        atomicAdd(&g_cnt[(b * NOFF + tid) * 2 + 0], s_diff[tid]);
        atomicAdd(&g_cnt[(b * NOFF + tid) * 2 + 1], s_n11[tid]);
    }

    // ---- last slab-block of this image finalizes ---------------------------
    if (tid == 0) {
        __threadfence();
        unsigned t = atomicAdd(&g_arrive[b], 1u);
        s_last = (t == SLABS - 1);
    }
    __syncthreads();

    if (s_last && tid < NOFF) {
        const int idx  = b * NOFF + tid;
        const int diff = atomicExch(&g_cnt[idx * 2 + 0], 0);   // read + reset
        const int n11  = atomicExch(&g_cnt[idx * 2 + 1], 0);
        if (tid == 0) atomicExch(&g_arrive[b], 0u);

        const int R  = RS[tid];
        const int Ca = CS[tid] < 0 ? -CS[tid] : CS[tid];
        const int N  = (HH - R) * (WW - Ca);
        const int n00 = N - n11 - diff;

        const float inv = 1.0f / (float)(2 * N - 4 * n00);
        float* o = out + (size_t)b * (NOFF * 4) + tid * 4;
        o[0] = (float)(4 * n00) * inv;
        const float v1 = (float)(2 * diff - 4 * n00) * inv;
        o[1] = v1;
        o[2] = v1;
        o[3] = (float)(2 * (N - 2 * diff)) * inv;
    }
}

extern "C" void kernel_launch(void* const* d_in, const int* in_sizes, int n_in,
                              void* d_out, int out_size)
{
    (void)n_in; (void)out_size; (void)in_sizes;
    dim3 grid(SLABS, NB);                       // 4 x 128 = 512 blocks
    glcm_fused<<<grid, NTH>>>((const float*)d_in[0], (float*)d_out);
}